// round 10
// baseline (speedup 1.0000x reference)
#include <cuda_runtime.h>
#include <cuda_bf16.h>
#include <stdint.h>

#define NN 100000
#define NE 1600000
#define NG 128
#define EPSV 1e-5f

// ---------------- scratch (device globals; no allocation allowed) ----------
__device__ float g_agg[(size_t)NN * 128];   // agg1 (first NN*8) then agg2
__device__ float g_x1 [(size_t)NN * 128];   // h1 -> x1 (in place, f32)
__device__ __nv_bfloat16 g_x1h[(size_t)NN * 128];  // x1 in bf16 (gather copy)
__device__ float g_h2 [(size_t)NN * 128];   // h2 (pre-BN)
__device__ int   g_deg [NN];
__device__ int   g_ptr [NN];
__device__ int   g_fill[NN];
__device__ int   g_srcs[NE];
__device__ float g_stat[512];               // sum1, sq1, sum2, sq2
__device__ uint32_t g_Bt[256 * 128];        // transposed [W2_l | W2_r], k-major, tf32 bits
__device__ float g_pool[NG * 128];
__device__ int   g_gcnt[NG];

__device__ __forceinline__ uint32_t f2tf(float f) {
    uint32_t u;
    asm("cvt.rna.tf32.f32 %0, %1;" : "=r"(u) : "f"(f));
    return u;
}

__device__ __forceinline__ void mma_tf32(float c[4], uint32_t a0, uint32_t a1,
                                         uint32_t a2, uint32_t a3,
                                         uint32_t b0, uint32_t b1) {
    asm volatile(
        "mma.sync.aligned.m16n8k8.row.col.f32.tf32.tf32.f32 "
        "{%0,%1,%2,%3},{%4,%5,%6,%7},{%8,%9},{%0,%1,%2,%3};\n"
        : "+f"(c[0]), "+f"(c[1]), "+f"(c[2]), "+f"(c[3])
        : "r"(a0), "r"(a1), "r"(a2), "r"(a3), "r"(b0), "r"(b1));
}

// ------------- init + weight transpose (merged, one launch) ----------------
// NOTE: grid must cover NN (deg reset) — the harness replays kernel_launch,
// so every scratch counter must be re-initialized every call.
__global__ void k_initw(const float* __restrict__ W2l, const float* __restrict__ W2r) {
    int i = blockIdx.x * blockDim.x + threadIdx.x;
    if (i < NN) g_deg[i] = 0;
    if (i < NG * 128) g_pool[i] = 0.f;
    if (i < 512) g_stat[i] = 0.f;
    if (i < NG) g_gcnt[i] = 0;
    if (i < 256 * 128) {
        int kg = i >> 7, c = i & 127;
        float v = (kg < 128) ? W2l[c * 128 + kg] : W2r[c * 128 + (kg - 128)];
        g_Bt[i] = f2tf(v);
    }
}

// ---------------- CSR build ----------------
__global__ void k_deg(const int* __restrict__ dst) {
    int e = blockIdx.x * blockDim.x + threadIdx.x;
    if (e < NE) atomicAdd(&g_deg[dst[e]], 1);
}

// single-block scan over NN degrees (1024 threads x 98 chunk)
#define SCB 1024
__global__ void __launch_bounds__(SCB) k_scan() {
    __shared__ int ssum[SCB];
    int t = threadIdx.x;
    const int CH = (NN + SCB - 1) / SCB;   // 98
    int beg = t * CH;
    int end = beg + CH < NN ? beg + CH : NN;
    int s = 0;
    for (int i = beg; i < end; i++) s += g_deg[i];
    ssum[t] = s;
    __syncthreads();
    for (int off = 1; off < SCB; off <<= 1) {
        int a = (t >= off) ? ssum[t - off] : 0;
        __syncthreads();
        ssum[t] += a;
        __syncthreads();
    }
    int run = ssum[t] - s;                 // exclusive prefix
    for (int i = beg; i < end; i++) {
        int d = g_deg[i];
        g_ptr[i] = run;
        g_fill[i] = run;
        run += d;
    }
}

__global__ void k_fill(const int* __restrict__ src, const int* __restrict__ dst) {
    int e = blockIdx.x * blockDim.x + threadIdx.x;
    if (e >= NE) return;
    int pos = atomicAdd(&g_fill[dst[e]], 1);
    g_srcs[pos] = src[e];
}

// ---------- layer 1 aggregation (F=8), thread per node, MLP=4 unroll -------
__global__ void k_agg1(const float* __restrict__ x) {
    int v = blockIdx.x * blockDim.x + threadIdx.x;
    if (v >= NN) return;
    int st = g_ptr[v], dg = g_deg[v];
    float a0 = 0, a1 = 0, a2 = 0, a3 = 0, a4 = 0, a5 = 0, a6 = 0, a7 = 0;
    int j = 0;
    for (; j + 4 <= dg; j += 4) {
        int s0 = g_srcs[st + j], s1 = g_srcs[st + j + 1];
        int s2 = g_srcs[st + j + 2], s3 = g_srcs[st + j + 3];
        float4 p0 = ((const float4*)(x + (size_t)s0 * 8))[0];
        float4 q0 = ((const float4*)(x + (size_t)s0 * 8))[1];
        float4 p1 = ((const float4*)(x + (size_t)s1 * 8))[0];
        float4 q1 = ((const float4*)(x + (size_t)s1 * 8))[1];
        float4 p2 = ((const float4*)(x + (size_t)s2 * 8))[0];
        float4 q2 = ((const float4*)(x + (size_t)s2 * 8))[1];
        float4 p3 = ((const float4*)(x + (size_t)s3 * 8))[0];
        float4 q3 = ((const float4*)(x + (size_t)s3 * 8))[1];
        a0 += p0.x + p1.x + p2.x + p3.x;
        a1 += p0.y + p1.y + p2.y + p3.y;
        a2 += p0.z + p1.z + p2.z + p3.z;
        a3 += p0.w + p1.w + p2.w + p3.w;
        a4 += q0.x + q1.x + q2.x + q3.x;
        a5 += q0.y + q1.y + q2.y + q3.y;
        a6 += q0.z + q1.z + q2.z + q3.z;
        a7 += q0.w + q1.w + q2.w + q3.w;
    }
    for (; j < dg; j++) {
        int s = g_srcs[st + j];
        float4 p = ((const float4*)(x + (size_t)s * 8))[0];
        float4 q = ((const float4*)(x + (size_t)s * 8))[1];
        a0 += p.x; a1 += p.y; a2 += p.z; a3 += p.w;
        a4 += q.x; a5 += q.y; a6 += q.z; a7 += q.w;
    }
    float inv = 1.f / fmaxf((float)dg, 1.f);
    float4* o = (float4*)(g_agg + (size_t)v * 8);
    o[0] = make_float4(a0 * inv, a1 * inv, a2 * inv, a3 * inv);
    o[1] = make_float4(a4 * inv, a5 * inv, a6 * inv, a7 * inv);
}

// ---------------- GEMM1 (K=16) + BN1 stats; thread = channel ---------------
__global__ void k_gemm1(const float* __restrict__ x,
                        const float* __restrict__ W1l, const float* __restrict__ b1,
                        const float* __restrict__ W1r) {
    __shared__ float sA[512];   // 64 nodes x 8 (agg1)
    __shared__ float sX[512];   // 64 nodes x 8 (x)
    int t = threadIdx.x;               // channel 0..127
    int n0 = blockIdx.x * 64;
    {
        int node = n0 + (t >> 1);
        float4 va = make_float4(0, 0, 0, 0), vx = va;
        if (node < NN) {
            va = ((const float4*)(g_agg + (size_t)n0 * 8))[t];
            vx = ((const float4*)(x + (size_t)n0 * 8))[t];
        }
        ((float4*)sA)[t] = va;
        ((float4*)sX)[t] = vx;
    }
    float wl[8], wr[8];
#pragma unroll
    for (int k = 0; k < 8; k++) { wl[k] = W1l[t * 8 + k]; wr[k] = W1r[t * 8 + k]; }
    float bc = b1[t];
    __syncthreads();
    float cs = 0.f, cq = 0.f;
    for (int v = 0; v < 64; v++) {
        int node = n0 + v;
        if (node >= NN) break;
        float acc = bc;
#pragma unroll
        for (int k = 0; k < 8; k++) acc += sA[v * 8 + k] * wl[k] + sX[v * 8 + k] * wr[k];
        g_x1[(size_t)node * 128 + t] = acc;
        cs += acc; cq += acc * acc;
    }
    atomicAdd(&g_stat[t], cs);
    atomicAdd(&g_stat[128 + t], cq);
}

// ------- BN1 + ReLU (f32 + bf16 copy) fused with pool(x1) + graph counts ---
// bnprep inlined: scale/shift recomputed per block from g_stat (cheap)
#define POOL_ROWS 128
__global__ void k_bn1pool(const int* __restrict__ batch,
                          const float* __restrict__ gamma,
                          const float* __restrict__ beta) {
    int c = threadIdx.x;            // channel
    int n0 = blockIdx.x * POOL_ROWS;
    float invN = 1.f / (float)NN;
    float mu = g_stat[c] * invN;
    float var = g_stat[128 + c] * invN - mu * mu;
    float sc = gamma[c] * rsqrtf(var + EPSV);
    float sh = beta[c] - mu * sc;
    float acc = 0.f;
    int curg = -1, cnt = 0;
    for (int r = 0; r < POOL_ROWS; r++) {
        int n = n0 + r;
        if (n >= NN) break;
        int gg = batch[n];
        if (gg != curg) {
            if (curg >= 0) {
                atomicAdd(&g_pool[curg * 128 + c], acc);
                if (c == 0) atomicAdd(&g_gcnt[curg], cnt);
            }
            curg = gg; acc = 0.f; cnt = 0;
        }
        float v = g_x1[(size_t)n * 128 + c];
        float u = fmaxf(v * sc + sh, 0.f);
        g_x1[(size_t)n * 128 + c]  = u;
        g_x1h[(size_t)n * 128 + c] = __float2bfloat16(u);
        acc += u; cnt++;
    }
    if (curg >= 0) {
        atomicAdd(&g_pool[curg * 128 + c], acc);
        if (c == 0) atomicAdd(&g_gcnt[curg], cnt);
    }
}

// --- layer 2 aggregation (F=128, bf16 gather), warp per node, MLP=4 --------
__global__ void k_agg2() {
    int warp = (blockIdx.x * blockDim.x + threadIdx.x) >> 5;
    int lane = threadIdx.x & 31;
    if (warp >= NN) return;
    int st = g_ptr[warp], dg = g_deg[warp];
    const uint2* base = (const uint2*)g_x1h;   // 4 bf16 per uint2; 32 per row
    float a0 = 0.f, a1 = 0.f, a2 = 0.f, a3 = 0.f;
    int j = 0;
    for (; j + 4 <= dg; j += 4) {
        int s0 = g_srcs[st + j],     s1 = g_srcs[st + j + 1];
        int s2 = g_srcs[st + j + 2], s3 = g_srcs[st + j + 3];
        uint2 v0 = base[(size_t)s0 * 32 + lane];
        uint2 v1 = base[(size_t)s1 * 32 + lane];
        uint2 v2 = base[(size_t)s2 * 32 + lane];
        uint2 v3 = base[(size_t)s3 * 32 + lane];
        float2 f;
        f = __bfloat1622float2(*(__nv_bfloat162*)&v0.x); a0 += f.x; a1 += f.y;
        f = __bfloat1622float2(*(__nv_bfloat162*)&v0.y); a2 += f.x; a3 += f.y;
        f = __bfloat1622float2(*(__nv_bfloat162*)&v1.x); a0 += f.x; a1 += f.y;
        f = __bfloat1622float2(*(__nv_bfloat162*)&v1.y); a2 += f.x; a3 += f.y;
        f = __bfloat1622float2(*(__nv_bfloat162*)&v2.x); a0 += f.x; a1 += f.y;
        f = __bfloat1622float2(*(__nv_bfloat162*)&v2.y); a2 += f.x; a3 += f.y;
        f = __bfloat1622float2(*(__nv_bfloat162*)&v3.x); a0 += f.x; a1 += f.y;
        f = __bfloat1622float2(*(__nv_bfloat162*)&v3.y); a2 += f.x; a3 += f.y;
    }
    for (; j < dg; j++) {
        int s = g_srcs[st + j];
        uint2 v = base[(size_t)s * 32 + lane];
        float2 f;
        f = __bfloat1622float2(*(__nv_bfloat162*)&v.x); a0 += f.x; a1 += f.y;
        f = __bfloat1622float2(*(__nv_bfloat162*)&v.y); a2 += f.x; a3 += f.y;
    }
    float inv = 1.f / fmaxf((float)dg, 1.f);
    ((float4*)(g_agg + (size_t)warp * 128))[lane] =
        make_float4(a0 * inv, a1 * inv, a2 * inv, a3 * inv);
}

// ---------------- GEMM2 (tf32 tensor cores) + fused BN2 stats --------------
__global__ void __launch_bounds__(256) k_gemm2(const float* __restrict__ b2) {
    __shared__ uint32_t sA[64][36];
    __shared__ uint32_t sB[32][136];
    __shared__ float s_stat[256];

    int t = threadIdx.x;
    int warp = t >> 5, lane = t & 31;
    int g = lane >> 2, tg = lane & 3;
    int wm = warp & 3, wn = warp >> 2;
    int n0 = blockIdx.x * 64;

    if (t < 256) s_stat[t] = 0.f;

    float c[8][4];
#pragma unroll
    for (int i = 0; i < 8; i++)
#pragma unroll
        for (int j = 0; j < 4; j++) c[i][j] = 0.f;

    for (int kc = 0; kc < 8; kc++) {
        {
            const float* base = (kc < 4) ? g_agg : g_x1;
            int koff = (kc & 3) * 32;
#pragma unroll
            for (int i = 0; i < 2; i++) {
                int idx = t + i * 256;
                int row = idx >> 3, kq = idx & 7;
                int node = n0 + row;
                float4 v = make_float4(0, 0, 0, 0);
                if (node < NN)
                    v = *(const float4*)(base + (size_t)node * 128 + koff + kq * 4);
                sA[row][kq * 4 + 0] = f2tf(v.x);
                sA[row][kq * 4 + 1] = f2tf(v.y);
                sA[row][kq * 4 + 2] = f2tf(v.z);
                sA[row][kq * 4 + 3] = f2tf(v.w);
            }
        }
        {
#pragma unroll
            for (int i = 0; i < 4; i++) {
                int idx = t + i * 256;
                int k = idx >> 5, nq = idx & 31;
                uint4 v = *(const uint4*)(g_Bt + (size_t)(kc * 32 + k) * 128 + nq * 4);
                *(uint4*)&sB[k][nq * 4] = v;
            }
        }
        __syncthreads();
#pragma unroll
        for (int ks = 0; ks < 4; ks++) {
            int k0 = ks * 8;
            uint32_t a0 = sA[wm * 16 + g    ][k0 + tg];
            uint32_t a1 = sA[wm * 16 + g + 8][k0 + tg];
            uint32_t a2 = sA[wm * 16 + g    ][k0 + tg + 4];
            uint32_t a3 = sA[wm * 16 + g + 8][k0 + tg + 4];
#pragma unroll
            for (int nt = 0; nt < 8; nt++) {
                uint32_t b0 = sB[k0 + tg    ][wn * 64 + nt * 8 + g];
                uint32_t b1 = sB[k0 + tg + 4][wn * 64 + nt * 8 + g];
                mma_tf32(c[nt], a0, a1, a2, a3, b0, b1);
            }
        }
        __syncthreads();
    }

    int r0 = n0 + wm * 16 + g;
    int r1 = r0 + 8;
#pragma unroll
    for (int nt = 0; nt < 8; nt++) {
        int col = wn * 64 + nt * 8 + tg * 2;
        float bv0 = b2[col], bv1 = b2[col + 1];
        float v00 = c[nt][0] + bv0, v01 = c[nt][1] + bv1;
        float v10 = c[nt][2] + bv0, v11 = c[nt][3] + bv1;
        float s0 = 0.f, s1 = 0.f, q0 = 0.f, q1 = 0.f;
        if (r0 < NN) {
            *(float2*)(g_h2 + (size_t)r0 * 128 + col) = make_float2(v00, v01);
            s0 += v00; q0 += v00 * v00;
            s1 += v01; q1 += v01 * v01;
        }
        if (r1 < NN) {
            *(float2*)(g_h2 + (size_t)r1 * 128 + col) = make_float2(v10, v11);
            s0 += v10; q0 += v10 * v10;
            s1 += v11; q1 += v11 * v11;
        }
        atomicAdd(&s_stat[col], s0);
        atomicAdd(&s_stat[col + 1], s1);
        atomicAdd(&s_stat[128 + col], q0);
        atomicAdd(&s_stat[128 + col + 1], q1);
    }
    __syncthreads();
    atomicAdd(&g_stat[256 + t], s_stat[t]);
}

// -------- BN2 + ReLU + pooling of x2 component (bnprep inlined) ------------
__global__ void k_pool2(const int* __restrict__ batch,
                        const float* __restrict__ gamma,
                        const float* __restrict__ beta) {
    int c = threadIdx.x;
    int n0 = blockIdx.x * POOL_ROWS;
    float invN = 1.f / (float)NN;
    float mu = g_stat[256 + c] * invN;
    float var = g_stat[384 + c] * invN - mu * mu;
    float sc = gamma[c] * rsqrtf(var + EPSV);
    float sh = beta[c] - mu * sc;
    float acc = 0.f;
    int curg = -1;
    for (int r = 0; r < POOL_ROWS; r++) {
        int n = n0 + r;
        if (n >= NN) break;
        int gg = batch[n];
        if (gg != curg) {
            if (curg >= 0) atomicAdd(&g_pool[curg * 128 + c], acc);
            curg = gg; acc = 0.f;
        }
        float h = g_h2[(size_t)n * 128 + c];
        acc += fmaxf(h * sc + sh, 0.f);
    }
    if (curg >= 0) atomicAdd(&g_pool[curg * 128 + c], acc);
}

__global__ void k_out(float* __restrict__ out) {
    int g = blockIdx.x, c = threadIdx.x;
    out[g * 128 + c] = g_pool[g * 128 + c] / fmaxf((float)g_gcnt[g], 1.f);
}

// ---------------- launch ----------------
extern "C" void kernel_launch(void* const* d_in, const int* in_sizes, int n_in,
                              void* d_out, int out_size) {
    const float* x     = (const float*)d_in[0];
    const int*   ei    = (const int*)d_in[1];      // [2, NE] int32
    const int*   batch = (const int*)d_in[2];
    const float* W1l   = (const float*)d_in[3];
    const float* b1    = (const float*)d_in[4];
    const float* W1r   = (const float*)d_in[5];
    const float* g1    = (const float*)d_in[6];
    const float* beta1 = (const float*)d_in[7];
    const float* W2l   = (const float*)d_in[8];
    const float* b2    = (const float*)d_in[9];
    const float* W2r   = (const float*)d_in[10];
    const float* g2    = (const float*)d_in[11];
    const float* beta2 = (const float*)d_in[12];
    float* out = (float*)d_out;

    const int* src = ei;
    const int* dst = ei + NE;

    k_initw<<<(NN + 255) / 256, 256>>>(W2l, W2r);   // grid MUST cover NN
    k_deg<<<(NE + 255) / 256, 256>>>(dst);
    k_scan<<<1, SCB>>>();
    k_fill<<<(NE + 255) / 256, 256>>>(src, dst);
    k_agg1<<<(NN + 255) / 256, 256>>>(x);
    k_gemm1<<<(NN + 63) / 64, 128>>>(x, W1l, b1, W1r);
    k_bn1pool<<<(NN + POOL_ROWS - 1) / POOL_ROWS, 128>>>(batch, g1, beta1);
    k_agg2<<<(NN * 32 + 255) / 256, 256>>>();
    k_gemm2<<<(NN + 63) / 64, 256>>>(b2);
    k_pool2<<<(NN + POOL_ROWS - 1) / POOL_ROWS, 128>>>(batch, g2, beta2);
    k_out<<<128, 128>>>(out);
}

// round 13
// speedup vs baseline: 1.4172x; 1.4172x over previous
#include <cuda_runtime.h>
#include <stdint.h>

#define NN 100000
#define NE 1600000
#define NG 128
#define EPSV 1e-5f

// ---------------- scratch (device globals; no allocation allowed) ----------
__device__ float g_agg[(size_t)NN * 128];   // agg1 (first NN*8) then agg2
__device__ float g_x1 [(size_t)NN * 128];   // h1 -> x1 (in place)
__device__ float g_h2 [(size_t)NN * 128];   // h2 (pre-BN)
__device__ int   g_deg [NN];
__device__ int   g_ptr [NN];
__device__ int   g_fill[NN];
__device__ int   g_srcs[NE];
__device__ int   g_bsum[256];
__device__ float g_stat[512];               // sum1, sq1, sum2, sq2
__device__ float g_bns [512];               // scale1, shift1, scale2, shift2
__device__ uint32_t g_Bt[256 * 128];        // transposed [W2_l | W2_r], k-major, tf32 bits
__device__ float g_pool[NG * 128];
__device__ int   g_gcnt[NG];

__device__ __forceinline__ uint32_t f2tf(float f) {
    uint32_t u;
    asm("cvt.rna.tf32.f32 %0, %1;" : "=r"(u) : "f"(f));
    return u;
}

__device__ __forceinline__ void mma_tf32(float c[4], uint32_t a0, uint32_t a1,
                                         uint32_t a2, uint32_t a3,
                                         uint32_t b0, uint32_t b1) {
    asm volatile(
        "mma.sync.aligned.m16n8k8.row.col.f32.tf32.tf32.f32 "
        "{%0,%1,%2,%3},{%4,%5,%6,%7},{%8,%9},{%0,%1,%2,%3};\n"
        : "+f"(c[0]), "+f"(c[1]), "+f"(c[2]), "+f"(c[3])
        : "r"(a0), "r"(a1), "r"(a2), "r"(a3), "r"(b0), "r"(b1));
}

// ------------- init + weight transpose (merged; grid covers NN!) -----------
__global__ void k_initw(const float* __restrict__ W2l, const float* __restrict__ W2r) {
    int i = blockIdx.x * blockDim.x + threadIdx.x;
    if (i < NN) g_deg[i] = 0;
    if (i < NG * 128) g_pool[i] = 0.f;
    if (i < 512) g_stat[i] = 0.f;
    if (i < NG) g_gcnt[i] = 0;
    if (i < 256 * 128) {
        int kg = i >> 7, c = i & 127;
        float v = (kg < 128) ? W2l[c * 128 + kg] : W2r[c * 128 + (kg - 128)];
        g_Bt[i] = f2tf(v);
    }
}

// ---------------- CSR build ----------------
__global__ void k_deg(const int* __restrict__ dst) {
    int e = blockIdx.x * blockDim.x + threadIdx.x;
    if (e < NE) atomicAdd(&g_deg[dst[e]], 1);
}

#define SCAN_T 512
__global__ void k_scan1() {
    __shared__ int s[SCAN_T];
    int t = threadIdx.x;
    int i = blockIdx.x * SCAN_T + t;
    int v = (i < NN) ? g_deg[i] : 0;
    s[t] = v;
    __syncthreads();
    for (int off = 1; off < SCAN_T; off <<= 1) {
        int a = (t >= off) ? s[t - off] : 0;
        __syncthreads();
        s[t] += a;
        __syncthreads();
    }
    if (i < NN) g_ptr[i] = s[t] - v;   // exclusive within block
    if (t == SCAN_T - 1) g_bsum[blockIdx.x] = s[t];
}
__global__ void k_scan2(int nblocks) {
    if (threadIdx.x == 0 && blockIdx.x == 0) {
        int run = 0;
        for (int b = 0; b < nblocks; b++) { int t = g_bsum[b]; g_bsum[b] = run; run += t; }
    }
}
__global__ void k_scan3() {
    int i = blockIdx.x * blockDim.x + threadIdx.x;
    if (i < NN) {
        int p = g_ptr[i] + g_bsum[i / SCAN_T];
        g_ptr[i] = p;
        g_fill[i] = p;                 // fill cursor pre-seeded to row start
    }
}
__global__ void k_fill(const int* __restrict__ src, const int* __restrict__ dst) {
    int e = blockIdx.x * blockDim.x + threadIdx.x;
    if (e >= NE) return;
    int pos = atomicAdd(&g_fill[dst[e]], 1);
    g_srcs[pos] = src[e];
}

// ---------------- layer 1 aggregation (F=8), thread per node ----------------
__global__ void k_agg1(const float* __restrict__ x) {
    int v = blockIdx.x * blockDim.x + threadIdx.x;
    if (v >= NN) return;
    int st = g_ptr[v], dg = g_deg[v];
    float4 a0 = make_float4(0, 0, 0, 0), a1 = make_float4(0, 0, 0, 0);
    for (int j = 0; j < dg; j++) {
        int s = g_srcs[st + j];
        const float4* xr = (const float4*)(x + (size_t)s * 8);
        float4 v0 = xr[0], v1 = xr[1];
        a0.x += v0.x; a0.y += v0.y; a0.z += v0.z; a0.w += v0.w;
        a1.x += v1.x; a1.y += v1.y; a1.z += v1.z; a1.w += v1.w;
    }
    float inv = 1.f / fmaxf((float)dg, 1.f);
    float4* o = (float4*)(g_agg + (size_t)v * 8);
    a0.x *= inv; a0.y *= inv; a0.z *= inv; a0.w *= inv;
    a1.x *= inv; a1.y *= inv; a1.z *= inv; a1.w *= inv;
    o[0] = a0; o[1] = a1;
}

// ---------------- GEMM1 (K=16) + BN1 stats; thread = channel ---------------
__global__ void k_gemm1(const float* __restrict__ x,
                        const float* __restrict__ W1l, const float* __restrict__ b1,
                        const float* __restrict__ W1r) {
    __shared__ float sA[512];   // 64 nodes x 8 (agg1)
    __shared__ float sX[512];   // 64 nodes x 8 (x)
    int t = threadIdx.x;               // channel 0..127
    int n0 = blockIdx.x * 64;
    {
        int node = n0 + (t >> 1);
        float4 va = make_float4(0, 0, 0, 0), vx = va;
        if (node < NN) {
            va = ((const float4*)(g_agg + (size_t)n0 * 8))[t];
            vx = ((const float4*)(x + (size_t)n0 * 8))[t];
        }
        ((float4*)sA)[t] = va;
        ((float4*)sX)[t] = vx;
    }
    float wl[8], wr[8];
#pragma unroll
    for (int k = 0; k < 8; k++) { wl[k] = W1l[t * 8 + k]; wr[k] = W1r[t * 8 + k]; }
    float bc = b1[t];
    __syncthreads();
    float cs = 0.f, cq = 0.f;
    for (int v = 0; v < 64; v++) {
        int node = n0 + v;
        if (node >= NN) break;
        float acc = bc;
#pragma unroll
        for (int k = 0; k < 8; k++) acc += sA[v * 8 + k] * wl[k] + sX[v * 8 + k] * wr[k];
        g_x1[(size_t)node * 128 + t] = acc;
        cs += acc; cq += acc * acc;
    }
    atomicAdd(&g_stat[t], cs);
    atomicAdd(&g_stat[128 + t], cq);
}

// ---------------- BN scale/shift precompute ----------------
__global__ void k_bnprep(int off, const float* __restrict__ gamma,
                         const float* __restrict__ beta) {
    int c = threadIdx.x;
    float invN = 1.f / (float)NN;
    float mu = g_stat[off + c] * invN;
    float var = g_stat[off + 128 + c] * invN - mu * mu;
    float s = gamma[c] * rsqrtf(var + EPSV);
    g_bns[off + c]       = s;
    g_bns[off + 128 + c] = beta[c] - mu * s;
}

// ---------------- BN1 + ReLU in place on g_x1 ----------------
__global__ void k_bn1() {
    const float4* sc4 = (const float4*)g_bns;
    const float4* sh4 = (const float4*)(g_bns + 128);
    int total = NN * 32;
    for (int i = blockIdx.x * blockDim.x + threadIdx.x; i < total; i += gridDim.x * blockDim.x) {
        int c4 = i & 31;
        float4 v = ((float4*)g_x1)[i];
        float4 sc = sc4[c4], sh = sh4[c4];
        v.x = fmaxf(v.x * sc.x + sh.x, 0.f);
        v.y = fmaxf(v.y * sc.y + sh.y, 0.f);
        v.z = fmaxf(v.z * sc.z + sh.z, 0.f);
        v.w = fmaxf(v.w * sc.w + sh.w, 0.f);
        ((float4*)g_x1)[i] = v;
    }
}

// ------ layer 2 aggregation (F=128), warp per node, 2 gathers in flight ----
__global__ void k_agg2() {
    int warp = (blockIdx.x * blockDim.x + threadIdx.x) >> 5;
    int lane = threadIdx.x & 31;
    if (warp >= NN) return;
    int st = g_ptr[warp], dg = g_deg[warp];
    float4 acc = make_float4(0, 0, 0, 0);
    int j = 0;
    for (; j + 2 <= dg; j += 2) {
        int s0 = g_srcs[st + j], s1 = g_srcs[st + j + 1];
        float4 v0 = ((const float4*)(g_x1 + (size_t)s0 * 128))[lane];
        float4 v1 = ((const float4*)(g_x1 + (size_t)s1 * 128))[lane];
        acc.x += v0.x + v1.x; acc.y += v0.y + v1.y;
        acc.z += v0.z + v1.z; acc.w += v0.w + v1.w;
    }
    if (j < dg) {
        int s = g_srcs[st + j];
        float4 v = ((const float4*)(g_x1 + (size_t)s * 128))[lane];
        acc.x += v.x; acc.y += v.y; acc.z += v.z; acc.w += v.w;
    }
    float inv = 1.f / fmaxf((float)dg, 1.f);
    acc.x *= inv; acc.y *= inv; acc.z *= inv; acc.w *= inv;
    ((float4*)(g_agg + (size_t)warp * 128))[lane] = acc;
}

// ---------------- GEMM2 (tf32 tensor cores) + fused BN2 stats --------------
// C[NN,128] = [agg2 | x1][NN,256] x Bt[256,128] + b2
// block: 256 threads = 8 warps (4 m-tiles x 2 n-halves); warp tile m16 x n64
__global__ void __launch_bounds__(256) k_gemm2(const float* __restrict__ b2) {
    __shared__ uint32_t sA[64][36];    // stride 36 -> conflict-free frag loads
    __shared__ uint32_t sB[32][136];   // stride 136 -> conflict-free frag loads
    __shared__ float s_stat[256];      // [0:128) sum, [128:256) sumsq

    int t = threadIdx.x;
    int warp = t >> 5, lane = t & 31;
    int g = lane >> 2, tg = lane & 3;
    int wm = warp & 3, wn = warp >> 2;
    int n0 = blockIdx.x * 64;

    if (t < 256) s_stat[t] = 0.f;

    float c[8][4];
#pragma unroll
    for (int i = 0; i < 8; i++)
#pragma unroll
        for (int j = 0; j < 4; j++) c[i][j] = 0.f;

    for (int kc = 0; kc < 8; kc++) {
        // A tile: 64 nodes x 32 k (from agg2 for kc<4, from x1 for kc>=4)
        {
            const float* base = (kc < 4) ? g_agg : g_x1;
            int koff = (kc & 3) * 32;
#pragma unroll
            for (int i = 0; i < 2; i++) {
                int idx = t + i * 256;          // 0..511 float4s
                int row = idx >> 3, kq = idx & 7;
                int node = n0 + row;
                float4 v = make_float4(0, 0, 0, 0);
                if (node < NN)
                    v = *(const float4*)(base + (size_t)node * 128 + koff + kq * 4);
                sA[row][kq * 4 + 0] = f2tf(v.x);
                sA[row][kq * 4 + 1] = f2tf(v.y);
                sA[row][kq * 4 + 2] = f2tf(v.z);
                sA[row][kq * 4 + 3] = f2tf(v.w);
            }
        }
        // B tile: 32 k x 128 n, already tf32 in g_Bt
        {
#pragma unroll
            for (int i = 0; i < 4; i++) {
                int idx = t + i * 256;          // 0..1023 uint4s
                int k = idx >> 5, nq = idx & 31;
                uint4 v = *(const uint4*)(g_Bt + (size_t)(kc * 32 + k) * 128 + nq * 4);
                *(uint4*)&sB[k][nq * 4] = v;
            }
        }
        __syncthreads();
#pragma unroll
        for (int ks = 0; ks < 4; ks++) {
            int k0 = ks * 8;
            uint32_t a0 = sA[wm * 16 + g    ][k0 + tg];
            uint32_t a1 = sA[wm * 16 + g + 8][k0 + tg];
            uint32_t a2 = sA[wm * 16 + g    ][k0 + tg + 4];
            uint32_t a3 = sA[wm * 16 + g + 8][k0 + tg + 4];
#pragma unroll
            for (int nt = 0; nt < 8; nt++) {
                uint32_t b0 = sB[k0 + tg    ][wn * 64 + nt * 8 + g];
                uint32_t b1 = sB[k0 + tg + 4][wn * 64 + nt * 8 + g];
                mma_tf32(c[nt], a0, a1, a2, a3, b0, b1);
            }
        }
        __syncthreads();
    }

    // epilogue: add bias, write h2, accumulate BN2 stats in smem
    int r0 = n0 + wm * 16 + g;
    int r1 = r0 + 8;
#pragma unroll
    for (int nt = 0; nt < 8; nt++) {
        int col = wn * 64 + nt * 8 + tg * 2;
        float bv0 = b2[col], bv1 = b2[col + 1];
        float v00 = c[nt][0] + bv0, v01 = c[nt][1] + bv1;   // row r0
        float v10 = c[nt][2] + bv0, v11 = c[nt][3] + bv1;   // row r1
        float s0 = 0.f, s1 = 0.f, q0 = 0.f, q1 = 0.f;
        if (r0 < NN) {
            *(float2*)(g_h2 + (size_t)r0 * 128 + col) = make_float2(v00, v01);
            s0 += v00; q0 += v00 * v00;
            s1 += v01; q1 += v01 * v01;
        }
        if (r1 < NN) {
            *(float2*)(g_h2 + (size_t)r1 * 128 + col) = make_float2(v10, v11);
            s0 += v10; q0 += v10 * v10;
            s1 += v11; q1 += v11 * v11;
        }
        atomicAdd(&s_stat[col], s0);
        atomicAdd(&s_stat[col + 1], s1);
        atomicAdd(&s_stat[128 + col], q0);
        atomicAdd(&s_stat[128 + col + 1], q1);
    }
    __syncthreads();
    atomicAdd(&g_stat[256 + t], s_stat[t]);
}

// ------- BN2 + ReLU + residual + pooling (batch sorted, register acc) ------
#define POOL_ROWS 128
__global__ void k_pool2(const int* __restrict__ batch) {
    int c = threadIdx.x;            // channel
    int n0 = blockIdx.x * POOL_ROWS;
    float sc = g_bns[256 + c], sh = g_bns[384 + c];
    float acc = 0.f;
    int curg = -1, cnt = 0;
    for (int r = 0; r < POOL_ROWS; r++) {
        int n = n0 + r;
        if (n >= NN) break;
        int gg = batch[n];
        if (gg != curg) {
            if (curg >= 0) {
                atomicAdd(&g_pool[curg * 128 + c], acc);
                if (c == 0) atomicAdd(&g_gcnt[curg], cnt);
            }
            curg = gg; acc = 0.f; cnt = 0;
        }
        float h = g_h2[(size_t)n * 128 + c];
        float xv = g_x1[(size_t)n * 128 + c];
        acc += xv + fmaxf(h * sc + sh, 0.f);
        cnt++;
    }
    if (curg >= 0) {
        atomicAdd(&g_pool[curg * 128 + c], acc);
        if (c == 0) atomicAdd(&g_gcnt[curg], cnt);
    }
}

__global__ void k_out(float* __restrict__ out) {
    int g = blockIdx.x, c = threadIdx.x;
    out[g * 128 + c] = g_pool[g * 128 + c] / fmaxf((float)g_gcnt[g], 1.f);
}

// ---------------- launch ----------------
extern "C" void kernel_launch(void* const* d_in, const int* in_sizes, int n_in,
                              void* d_out, int out_size) {
    const float* x     = (const float*)d_in[0];
    const int*   ei    = (const int*)d_in[1];      // [2, NE] int32
    const int*   batch = (const int*)d_in[2];
    const float* W1l   = (const float*)d_in[3];
    const float* b1    = (const float*)d_in[4];
    const float* W1r   = (const float*)d_in[5];
    const float* g1    = (const float*)d_in[6];
    const float* beta1 = (const float*)d_in[7];
    const float* W2l   = (const float*)d_in[8];
    const float* b2    = (const float*)d_in[9];
    const float* W2r   = (const float*)d_in[10];
    const float* g2    = (const float*)d_in[11];
    const float* beta2 = (const float*)d_in[12];
    float* out = (float*)d_out;

    const int* src = ei;
    const int* dst = ei + NE;

    int nScan = (NN + SCAN_T - 1) / SCAN_T;

    k_initw<<<(NN + 255) / 256, 256>>>(W2l, W2r);   // grid covers NN
    k_deg<<<(NE + 255) / 256, 256>>>(dst);
    k_scan1<<<nScan, SCAN_T>>>();
    k_scan2<<<1, 1>>>(nScan);
    k_scan3<<<(NN + 255) / 256, 256>>>();
    k_fill<<<(NE + 255) / 256, 256>>>(src, dst);
    k_agg1<<<(NN + 255) / 256, 256>>>(x);
    k_gemm1<<<(NN + 63) / 64, 128>>>(x, W1l, b1, W1r);
    k_bnprep<<<1, 128>>>(0, g1, beta1);
    k_bn1<<<1024, 256>>>();
    k_agg2<<<(NN * 32 + 255) / 256, 256>>>();
    k_gemm2<<<(NN + 63) / 64, 256>>>(b2);
    k_bnprep<<<1, 128>>>(256, g2, beta2);
    k_pool2<<<(NN + POOL_ROWS - 1) / POOL_ROWS, 128>>>(batch);
    k_out<<<128, 128>>>(out);
}

// round 14
// speedup vs baseline: 1.4231x; 1.0041x over previous
#include <cuda_runtime.h>
#include <stdint.h>

#define NN 100000
#define NE 1600000
#define NG 128
#define EPSV 1e-5f

// ---------------- scratch (device globals; no allocation allowed) ----------
__device__ float g_agg[(size_t)NN * 128];   // agg1 (first NN*8) then agg2
__device__ float g_x1 [(size_t)NN * 128];   // h1 -> x1 (in place)
__device__ float g_h2 [(size_t)NN * 128];   // h2 (pre-BN)
__device__ int   g_deg [NN];
__device__ int   g_ptr [NN];
__device__ int   g_fill[NN];
__device__ int   g_srcs[NE];
__device__ int   g_bsum[256];
__device__ float g_stat[512];               // sum1, sq1, sum2, sq2
__device__ float g_bns [512];               // scale1, shift1, scale2, shift2
__device__ uint32_t g_Bt[256 * 128];        // transposed [W2_l | W2_r], k-major, tf32 bits
__device__ float g_pool[NG * 128];
__device__ int   g_gcnt[NG];

__device__ __forceinline__ uint32_t f2tf(float f) {
    uint32_t u;
    asm("cvt.rna.tf32.f32 %0, %1;" : "=r"(u) : "f"(f));
    return u;
}

__device__ __forceinline__ void mma_tf32(float c[4], uint32_t a0, uint32_t a1,
                                         uint32_t a2, uint32_t a3,
                                         uint32_t b0, uint32_t b1) {
    asm volatile(
        "mma.sync.aligned.m16n8k8.row.col.f32.tf32.tf32.f32 "
        "{%0,%1,%2,%3},{%4,%5,%6,%7},{%8,%9},{%0,%1,%2,%3};\n"
        : "+f"(c[0]), "+f"(c[1]), "+f"(c[2]), "+f"(c[3])
        : "r"(a0), "r"(a1), "r"(a2), "r"(a3), "r"(b0), "r"(b1));
}

// ------------- init + weight transpose (merged; grid covers NN!) -----------
__global__ void k_initw(const float* __restrict__ W2l, const float* __restrict__ W2r) {
    int i = blockIdx.x * blockDim.x + threadIdx.x;
    if (i < NN) g_deg[i] = 0;
    if (i < NG * 128) g_pool[i] = 0.f;
    if (i < 512) g_stat[i] = 0.f;
    if (i < NG) g_gcnt[i] = 0;
    if (i < 256 * 128) {
        int kg = i >> 7, c = i & 127;
        float v = (kg < 128) ? W2l[c * 128 + kg] : W2r[c * 128 + (kg - 128)];
        g_Bt[i] = f2tf(v);
    }
}

// ---------------- CSR build ----------------
__global__ void k_deg(const int* __restrict__ dst) {
    int e = blockIdx.x * blockDim.x + threadIdx.x;
    if (e < NE) atomicAdd(&g_deg[dst[e]], 1);
}

#define SCAN_T 512
__global__ void k_scan1() {
    __shared__ int s[SCAN_T];
    int t = threadIdx.x;
    int i = blockIdx.x * SCAN_T + t;
    int v = (i < NN) ? g_deg[i] : 0;
    s[t] = v;
    __syncthreads();
    for (int off = 1; off < SCAN_T; off <<= 1) {
        int a = (t >= off) ? s[t - off] : 0;
        __syncthreads();
        s[t] += a;
        __syncthreads();
    }
    if (i < NN) g_ptr[i] = s[t] - v;   // exclusive within block
    if (t == SCAN_T - 1) g_bsum[blockIdx.x] = s[t];
}
__global__ void k_scan2(int nblocks) {
    if (threadIdx.x == 0 && blockIdx.x == 0) {
        int run = 0;
        for (int b = 0; b < nblocks; b++) { int t = g_bsum[b]; g_bsum[b] = run; run += t; }
    }
}
__global__ void k_scan3() {
    int i = blockIdx.x * blockDim.x + threadIdx.x;
    if (i < NN) {
        int p = g_ptr[i] + g_bsum[i / SCAN_T];
        g_ptr[i] = p;
        g_fill[i] = p;                 // fill cursor pre-seeded to row start
    }
}
__global__ void k_fill(const int* __restrict__ src, const int* __restrict__ dst) {
    int e = blockIdx.x * blockDim.x + threadIdx.x;
    if (e >= NE) return;
    int pos = atomicAdd(&g_fill[dst[e]], 1);
    g_srcs[pos] = src[e];
}

// ---------------- layer 1 aggregation (F=8), thread per node ----------------
__global__ void k_agg1(const float* __restrict__ x) {
    int v = blockIdx.x * blockDim.x + threadIdx.x;
    if (v >= NN) return;
    int st = g_ptr[v], dg = g_deg[v];
    float4 a0 = make_float4(0, 0, 0, 0), a1 = make_float4(0, 0, 0, 0);
    for (int j = 0; j < dg; j++) {
        int s = g_srcs[st + j];
        const float4* xr = (const float4*)(x + (size_t)s * 8);
        float4 v0 = xr[0], v1 = xr[1];
        a0.x += v0.x; a0.y += v0.y; a0.z += v0.z; a0.w += v0.w;
        a1.x += v1.x; a1.y += v1.y; a1.z += v1.z; a1.w += v1.w;
    }
    float inv = 1.f / fmaxf((float)dg, 1.f);
    float4* o = (float4*)(g_agg + (size_t)v * 8);
    a0.x *= inv; a0.y *= inv; a0.z *= inv; a0.w *= inv;
    a1.x *= inv; a1.y *= inv; a1.z *= inv; a1.w *= inv;
    o[0] = a0; o[1] = a1;
}

// ---------------- GEMM1 (K=16) + BN1 stats; thread = channel ---------------
__global__ void k_gemm1(const float* __restrict__ x,
                        const float* __restrict__ W1l, const float* __restrict__ b1,
                        const float* __restrict__ W1r) {
    __shared__ float sA[512];   // 64 nodes x 8 (agg1)
    __shared__ float sX[512];   // 64 nodes x 8 (x)
    int t = threadIdx.x;               // channel 0..127
    int n0 = blockIdx.x * 64;
    {
        int node = n0 + (t >> 1);
        float4 va = make_float4(0, 0, 0, 0), vx = va;
        if (node < NN) {
            va = ((const float4*)(g_agg + (size_t)n0 * 8))[t];
            vx = ((const float4*)(x + (size_t)n0 * 8))[t];
        }
        ((float4*)sA)[t] = va;
        ((float4*)sX)[t] = vx;
    }
    float wl[8], wr[8];
#pragma unroll
    for (int k = 0; k < 8; k++) { wl[k] = W1l[t * 8 + k]; wr[k] = W1r[t * 8 + k]; }
    float bc = b1[t];
    __syncthreads();
    float cs = 0.f, cq = 0.f;
    for (int v = 0; v < 64; v++) {
        int node = n0 + v;
        if (node >= NN) break;
        float acc = bc;
#pragma unroll
        for (int k = 0; k < 8; k++) acc += sA[v * 8 + k] * wl[k] + sX[v * 8 + k] * wr[k];
        g_x1[(size_t)node * 128 + t] = acc;
        cs += acc; cq += acc * acc;
    }
    atomicAdd(&g_stat[t], cs);
    atomicAdd(&g_stat[128 + t], cq);
}

// ---------------- BN scale/shift precompute ----------------
__global__ void k_bnprep(int off, const float* __restrict__ gamma,
                         const float* __restrict__ beta) {
    int c = threadIdx.x;
    float invN = 1.f / (float)NN;
    float mu = g_stat[off + c] * invN;
    float var = g_stat[off + 128 + c] * invN - mu * mu;
    float s = gamma[c] * rsqrtf(var + EPSV);
    g_bns[off + c]       = s;
    g_bns[off + 128 + c] = beta[c] - mu * s;
}

// ---------------- BN1 + ReLU in place on g_x1 ----------------
__global__ void k_bn1() {
    const float4* sc4 = (const float4*)g_bns;
    const float4* sh4 = (const float4*)(g_bns + 128);
    int total = NN * 32;
    for (int i = blockIdx.x * blockDim.x + threadIdx.x; i < total; i += gridDim.x * blockDim.x) {
        int c4 = i & 31;
        float4 v = ((float4*)g_x1)[i];
        float4 sc = sc4[c4], sh = sh4[c4];
        v.x = fmaxf(v.x * sc.x + sh.x, 0.f);
        v.y = fmaxf(v.y * sc.y + sh.y, 0.f);
        v.z = fmaxf(v.z * sc.z + sh.z, 0.f);
        v.w = fmaxf(v.w * sc.w + sh.w, 0.f);
        ((float4*)g_x1)[i] = v;
    }
}

// ------ layer 2 aggregation (F=128), warp per node, 2 gathers in flight ----
__global__ void k_agg2() {
    int warp = (blockIdx.x * blockDim.x + threadIdx.x) >> 5;
    int lane = threadIdx.x & 31;
    if (warp >= NN) return;
    int st = g_ptr[warp], dg = g_deg[warp];
    float4 acc = make_float4(0, 0, 0, 0);
    int j = 0;
    for (; j + 2 <= dg; j += 2) {
        int s0 = g_srcs[st + j], s1 = g_srcs[st + j + 1];
        float4 v0 = ((const float4*)(g_x1 + (size_t)s0 * 128))[lane];
        float4 v1 = ((const float4*)(g_x1 + (size_t)s1 * 128))[lane];
        acc.x += v0.x + v1.x; acc.y += v0.y + v1.y;
        acc.z += v0.z + v1.z; acc.w += v0.w + v1.w;
    }
    if (j < dg) {
        int s = g_srcs[st + j];
        float4 v = ((const float4*)(g_x1 + (size_t)s * 128))[lane];
        acc.x += v.x; acc.y += v.y; acc.z += v.z; acc.w += v.w;
    }
    float inv = 1.f / fmaxf((float)dg, 1.f);
    acc.x *= inv; acc.y *= inv; acc.z *= inv; acc.w *= inv;
    ((float4*)(g_agg + (size_t)warp * 128))[lane] = acc;
}

// ---------------- GEMM2 (tf32 tensor cores) + fused BN2 stats --------------
// C[NN,128] = [agg2 | x1][NN,256] x Bt[256,128] + b2
// block: 256 threads = 8 warps (4 m-tiles x 2 n-halves); warp tile m16 x n64
__global__ void __launch_bounds__(256) k_gemm2(const float* __restrict__ b2) {
    __shared__ uint32_t sA[64][36];    // stride 36 -> conflict-free frag loads
    __shared__ uint32_t sB[32][136];   // stride 136 -> conflict-free frag loads
    __shared__ float s_stat[256];      // [0:128) sum, [128:256) sumsq

    int t = threadIdx.x;
    int warp = t >> 5, lane = t & 31;
    int g = lane >> 2, tg = lane & 3;
    int wm = warp & 3, wn = warp >> 2;
    int n0 = blockIdx.x * 64;

    if (t < 256) s_stat[t] = 0.f;

    float c[8][4];
#pragma unroll
    for (int i = 0; i < 8; i++)
#pragma unroll
        for (int j = 0; j < 4; j++) c[i][j] = 0.f;

    for (int kc = 0; kc < 8; kc++) {
        // A tile: 64 nodes x 32 k (from agg2 for kc<4, from x1 for kc>=4)
        {
            const float* base = (kc < 4) ? g_agg : g_x1;
            int koff = (kc & 3) * 32;
#pragma unroll
            for (int i = 0; i < 2; i++) {
                int idx = t + i * 256;          // 0..511 float4s
                int row = idx >> 3, kq = idx & 7;
                int node = n0 + row;
                float4 v = make_float4(0, 0, 0, 0);
                if (node < NN)
                    v = *(const float4*)(base + (size_t)node * 128 + koff + kq * 4);
                sA[row][kq * 4 + 0] = f2tf(v.x);
                sA[row][kq * 4 + 1] = f2tf(v.y);
                sA[row][kq * 4 + 2] = f2tf(v.z);
                sA[row][kq * 4 + 3] = f2tf(v.w);
            }
        }
        // B tile: 32 k x 128 n, already tf32 in g_Bt
        {
#pragma unroll
            for (int i = 0; i < 4; i++) {
                int idx = t + i * 256;          // 0..1023 uint4s
                int k = idx >> 5, nq = idx & 31;
                uint4 v = *(const uint4*)(g_Bt + (size_t)(kc * 32 + k) * 128 + nq * 4);
                *(uint4*)&sB[k][nq * 4] = v;
            }
        }
        __syncthreads();
#pragma unroll
        for (int ks = 0; ks < 4; ks++) {
            int k0 = ks * 8;
            uint32_t a0 = sA[wm * 16 + g    ][k0 + tg];
            uint32_t a1 = sA[wm * 16 + g + 8][k0 + tg];
            uint32_t a2 = sA[wm * 16 + g    ][k0 + tg + 4];
            uint32_t a3 = sA[wm * 16 + g + 8][k0 + tg + 4];
#pragma unroll
            for (int nt = 0; nt < 8; nt++) {
                uint32_t b0 = sB[k0 + tg    ][wn * 64 + nt * 8 + g];
                uint32_t b1 = sB[k0 + tg + 4][wn * 64 + nt * 8 + g];
                mma_tf32(c[nt], a0, a1, a2, a3, b0, b1);
            }
        }
        __syncthreads();
    }

    // epilogue: add bias, write h2, accumulate BN2 stats in smem
    int r0 = n0 + wm * 16 + g;
    int r1 = r0 + 8;
#pragma unroll
    for (int nt = 0; nt < 8; nt++) {
        int col = wn * 64 + nt * 8 + tg * 2;
        float bv0 = b2[col], bv1 = b2[col + 1];
        float v00 = c[nt][0] + bv0, v01 = c[nt][1] + bv1;   // row r0
        float v10 = c[nt][2] + bv0, v11 = c[nt][3] + bv1;   // row r1
        float s0 = 0.f, s1 = 0.f, q0 = 0.f, q1 = 0.f;
        if (r0 < NN) {
            *(float2*)(g_h2 + (size_t)r0 * 128 + col) = make_float2(v00, v01);
            s0 += v00; q0 += v00 * v00;
            s1 += v01; q1 += v01 * v01;
        }
        if (r1 < NN) {
            *(float2*)(g_h2 + (size_t)r1 * 128 + col) = make_float2(v10, v11);
            s0 += v10; q0 += v10 * v10;
            s1 += v11; q1 += v11 * v11;
        }
        atomicAdd(&s_stat[col], s0);
        atomicAdd(&s_stat[col + 1], s1);
        atomicAdd(&s_stat[128 + col], q0);
        atomicAdd(&s_stat[128 + col + 1], q1);
    }
    __syncthreads();
    atomicAdd(&g_stat[256 + t], s_stat[t]);
}

// ------- BN2 + ReLU + residual + pooling (batch sorted, register acc) ------
#define POOL_ROWS 128
__global__ void k_pool2(const int* __restrict__ batch) {
    int c = threadIdx.x;            // channel
    int n0 = blockIdx.x * POOL_ROWS;
    float sc = g_bns[256 + c], sh = g_bns[384 + c];
    float acc = 0.f;
    int curg = -1, cnt = 0;
    for (int r = 0; r < POOL_ROWS; r++) {
        int n = n0 + r;
        if (n >= NN) break;
        int gg = batch[n];
        if (gg != curg) {
            if (curg >= 0) {
                atomicAdd(&g_pool[curg * 128 + c], acc);
                if (c == 0) atomicAdd(&g_gcnt[curg], cnt);
            }
            curg = gg; acc = 0.f; cnt = 0;
        }
        float h = g_h2[(size_t)n * 128 + c];
        float xv = g_x1[(size_t)n * 128 + c];
        acc += xv + fmaxf(h * sc + sh, 0.f);
        cnt++;
    }
    if (curg >= 0) {
        atomicAdd(&g_pool[curg * 128 + c], acc);
        if (c == 0) atomicAdd(&g_gcnt[curg], cnt);
    }
}

__global__ void k_out(float* __restrict__ out) {
    int g = blockIdx.x, c = threadIdx.x;
    out[g * 128 + c] = g_pool[g * 128 + c] / fmaxf((float)g_gcnt[g], 1.f);
}

// ---------------- launch ----------------
extern "C" void kernel_launch(void* const* d_in, const int* in_sizes, int n_in,
                              void* d_out, int out_size) {
    const float* x     = (const float*)d_in[0];
    const int*   ei    = (const int*)d_in[1];      // [2, NE] int32
    const int*   batch = (const int*)d_in[2];
    const float* W1l   = (const float*)d_in[3];
    const float* b1    = (const float*)d_in[4];
    const float* W1r   = (const float*)d_in[5];
    const float* g1    = (const float*)d_in[6];
    const float* beta1 = (const float*)d_in[7];
    const float* W2l   = (const float*)d_in[8];
    const float* b2    = (const float*)d_in[9];
    const float* W2r   = (const float*)d_in[10];
    const float* g2    = (const float*)d_in[11];
    const float* beta2 = (const float*)d_in[12];
    float* out = (float*)d_out;

    const int* src = ei;
    const int* dst = ei + NE;

    int nScan = (NN + SCAN_T - 1) / SCAN_T;

    k_initw<<<(NN + 255) / 256, 256>>>(W2l, W2r);   // grid covers NN
    k_deg<<<(NE + 255) / 256, 256>>>(dst);
    k_scan1<<<nScan, SCAN_T>>>();
    k_scan2<<<1, 1>>>(nScan);
    k_scan3<<<(NN + 255) / 256, 256>>>();
    k_fill<<<(NE + 255) / 256, 256>>>(src, dst);
    k_agg1<<<(NN + 255) / 256, 256>>>(x);
    k_gemm1<<<(NN + 63) / 64, 128>>>(x, W1l, b1, W1r);
    k_bnprep<<<1, 128>>>(0, g1, beta1);
    k_bn1<<<1024, 256>>>();
    k_agg2<<<(NN * 32 + 255) / 256, 256>>>();
    k_gemm2<<<(NN + 63) / 64, 256>>>(b2);
    k_bnprep<<<1, 128>>>(256, g2, beta2);
    k_pool2<<<(NN + POOL_ROWS - 1) / POOL_ROWS, 128>>>(batch);
    k_out<<<128, 128>>>(out);
}

// round 16
// speedup vs baseline: 1.4797x; 1.0398x over previous
#include <cuda_runtime.h>
#include <stdint.h>

#define NN 100000
#define NE 1600000
#define NG 128
#define EPSV 1e-5f

// ---------------- scratch (device globals; no allocation allowed) ----------
__device__ float g_agg[(size_t)NN * 128];   // agg1 (first NN*8) then agg2
__device__ float g_x1 [(size_t)NN * 128];   // h1 (PRE-BN; BN1+relu applied at read)
__device__ float g_h2 [(size_t)NN * 128];   // h2 (pre-BN)
__device__ int   g_deg [NN];
__device__ int   g_ptr [NN];
__device__ int   g_fill[NN];
__device__ int   g_srcs[NE];
__device__ int   g_bsum[256];
__device__ float g_stat[512];               // sum1, sq1, sum2, sq2
__device__ float g_bns [512];               // scale1, shift1, scale2, shift2
__device__ uint32_t g_Bt[256 * 128];        // transposed [W2_l | W2_r], k-major, tf32 bits
__device__ float g_pool[NG * 128];
__device__ int   g_gcnt[NG];

__device__ __forceinline__ uint32_t f2tf(float f) {
    uint32_t u;
    asm("cvt.rna.tf32.f32 %0, %1;" : "=r"(u) : "f"(f));
    return u;
}

__device__ __forceinline__ void mma_tf32(float c[4], uint32_t a0, uint32_t a1,
                                         uint32_t a2, uint32_t a3,
                                         uint32_t b0, uint32_t b1) {
    asm volatile(
        "mma.sync.aligned.m16n8k8.row.col.f32.tf32.tf32.f32 "
        "{%0,%1,%2,%3},{%4,%5,%6,%7},{%8,%9},{%0,%1,%2,%3};\n"
        : "+f"(c[0]), "+f"(c[1]), "+f"(c[2]), "+f"(c[3])
        : "r"(a0), "r"(a1), "r"(a2), "r"(a3), "r"(b0), "r"(b1));
}

// ------------- init + weight transpose (merged; grid covers NN!) -----------
__global__ void k_initw(const float* __restrict__ W2l, const float* __restrict__ W2r) {
    int i = blockIdx.x * blockDim.x + threadIdx.x;
    if (i < NN) g_deg[i] = 0;
    if (i < NG * 128) g_pool[i] = 0.f;
    if (i < 512) g_stat[i] = 0.f;
    if (i < NG) g_gcnt[i] = 0;
    if (i < 256 * 128) {
        int kg = i >> 7, c = i & 127;
        float v = (kg < 128) ? W2l[c * 128 + kg] : W2r[c * 128 + (kg - 128)];
        g_Bt[i] = f2tf(v);
    }
}

// ---------------- CSR build ----------------
__global__ void k_deg(const int* __restrict__ dst) {
    int e = blockIdx.x * blockDim.x + threadIdx.x;
    if (e < NE) atomicAdd(&g_deg[dst[e]], 1);
}

#define SCAN_T 512
__global__ void k_scan1() {
    __shared__ int s[SCAN_T];
    int t = threadIdx.x;
    int i = blockIdx.x * SCAN_T + t;
    int v = (i < NN) ? g_deg[i] : 0;
    s[t] = v;
    __syncthreads();
    for (int off = 1; off < SCAN_T; off <<= 1) {
        int a = (t >= off) ? s[t - off] : 0;
        __syncthreads();
        s[t] += a;
        __syncthreads();
    }
    if (i < NN) g_ptr[i] = s[t] - v;   // exclusive within block
    if (t == SCAN_T - 1) g_bsum[blockIdx.x] = s[t];
}
// block-parallel scan over the <=256 block sums (replaces 1-thread version)
__global__ void k_scan2(int nblocks) {
    __shared__ int s[256];
    int t = threadIdx.x;
    int v = (t < nblocks) ? g_bsum[t] : 0;
    s[t] = v;
    __syncthreads();
    for (int off = 1; off < 256; off <<= 1) {
        int a = (t >= off) ? s[t - off] : 0;
        __syncthreads();
        s[t] += a;
        __syncthreads();
    }
    if (t < nblocks) g_bsum[t] = s[t] - v;   // exclusive
}
__global__ void k_scan3() {
    int i = blockIdx.x * blockDim.x + threadIdx.x;
    if (i < NN) {
        int p = g_ptr[i] + g_bsum[i / SCAN_T];
        g_ptr[i] = p;
        g_fill[i] = p;                 // fill cursor pre-seeded to row start
    }
}
__global__ void k_fill(const int* __restrict__ src, const int* __restrict__ dst) {
    int e = blockIdx.x * blockDim.x + threadIdx.x;
    if (e >= NE) return;
    int pos = atomicAdd(&g_fill[dst[e]], 1);
    g_srcs[pos] = src[e];
}

// ---------------- layer 1 aggregation (F=8), thread per node ----------------
__global__ void k_agg1(const float* __restrict__ x) {
    int v = blockIdx.x * blockDim.x + threadIdx.x;
    if (v >= NN) return;
    int st = g_ptr[v], dg = g_deg[v];
    float4 a0 = make_float4(0, 0, 0, 0), a1 = make_float4(0, 0, 0, 0);
    for (int j = 0; j < dg; j++) {
        int s = g_srcs[st + j];
        const float4* xr = (const float4*)(x + (size_t)s * 8);
        float4 v0 = xr[0], v1 = xr[1];
        a0.x += v0.x; a0.y += v0.y; a0.z += v0.z; a0.w += v0.w;
        a1.x += v1.x; a1.y += v1.y; a1.z += v1.z; a1.w += v1.w;
    }
    float inv = 1.f / fmaxf((float)dg, 1.f);
    float4* o = (float4*)(g_agg + (size_t)v * 8);
    a0.x *= inv; a0.y *= inv; a0.z *= inv; a0.w *= inv;
    a1.x *= inv; a1.y *= inv; a1.z *= inv; a1.w *= inv;
    o[0] = a0; o[1] = a1;
}

// ---------------- GEMM1 (K=16) + BN1 stats; thread = channel ---------------
__global__ void k_gemm1(const float* __restrict__ x,
                        const float* __restrict__ W1l, const float* __restrict__ b1,
                        const float* __restrict__ W1r) {
    __shared__ float sA[512];   // 64 nodes x 8 (agg1)
    __shared__ float sX[512];   // 64 nodes x 8 (x)
    int t = threadIdx.x;               // channel 0..127
    int n0 = blockIdx.x * 64;
    {
        int node = n0 + (t >> 1);
        float4 va = make_float4(0, 0, 0, 0), vx = va;
        if (node < NN) {
            va = ((const float4*)(g_agg + (size_t)n0 * 8))[t];
            vx = ((const float4*)(x + (size_t)n0 * 8))[t];
        }
        ((float4*)sA)[t] = va;
        ((float4*)sX)[t] = vx;
    }
    float wl[8], wr[8];
#pragma unroll
    for (int k = 0; k < 8; k++) { wl[k] = W1l[t * 8 + k]; wr[k] = W1r[t * 8 + k]; }
    float bc = b1[t];
    __syncthreads();
    float cs = 0.f, cq = 0.f;
    for (int v = 0; v < 64; v++) {
        int node = n0 + v;
        if (node >= NN) break;
        float acc = bc;
#pragma unroll
        for (int k = 0; k < 8; k++) acc += sA[v * 8 + k] * wl[k] + sX[v * 8 + k] * wr[k];
        g_x1[(size_t)node * 128 + t] = acc;
        cs += acc; cq += acc * acc;
    }
    atomicAdd(&g_stat[t], cs);
    atomicAdd(&g_stat[128 + t], cq);
}

// ---------------- BN scale/shift precompute ----------------
__global__ void k_bnprep(int off, const float* __restrict__ gamma,
                         const float* __restrict__ beta) {
    int c = threadIdx.x;
    float invN = 1.f / (float)NN;
    float mu = g_stat[off + c] * invN;
    float var = g_stat[off + 128 + c] * invN - mu * mu;
    float s = gamma[c] * rsqrtf(var + EPSV);
    g_bns[off + c]       = s;
    g_bns[off + 128 + c] = beta[c] - mu * s;
}

// ------ layer 2 aggregation; BN1+relu applied ON THE FLY to gathered x1 ----
__global__ void k_agg2() {
    int warp = (blockIdx.x * blockDim.x + threadIdx.x) >> 5;
    int lane = threadIdx.x & 31;
    if (warp >= NN) return;
    float4 sc = ((const float4*)g_bns)[lane];          // channels lane*4..+3
    float4 sh = ((const float4*)(g_bns + 128))[lane];
    int st = g_ptr[warp], dg = g_deg[warp];
    float4 acc = make_float4(0, 0, 0, 0);
    int j = 0;
    for (; j + 2 <= dg; j += 2) {
        int s0 = g_srcs[st + j], s1 = g_srcs[st + j + 1];
        float4 v0 = ((const float4*)(g_x1 + (size_t)s0 * 128))[lane];
        float4 v1 = ((const float4*)(g_x1 + (size_t)s1 * 128))[lane];
        acc.x += fmaxf(v0.x * sc.x + sh.x, 0.f) + fmaxf(v1.x * sc.x + sh.x, 0.f);
        acc.y += fmaxf(v0.y * sc.y + sh.y, 0.f) + fmaxf(v1.y * sc.y + sh.y, 0.f);
        acc.z += fmaxf(v0.z * sc.z + sh.z, 0.f) + fmaxf(v1.z * sc.z + sh.z, 0.f);
        acc.w += fmaxf(v0.w * sc.w + sh.w, 0.f) + fmaxf(v1.w * sc.w + sh.w, 0.f);
    }
    if (j < dg) {
        int s = g_srcs[st + j];
        float4 v = ((const float4*)(g_x1 + (size_t)s * 128))[lane];
        acc.x += fmaxf(v.x * sc.x + sh.x, 0.f);
        acc.y += fmaxf(v.y * sc.y + sh.y, 0.f);
        acc.z += fmaxf(v.z * sc.z + sh.z, 0.f);
        acc.w += fmaxf(v.w * sc.w + sh.w, 0.f);
    }
    float inv = 1.f / fmaxf((float)dg, 1.f);
    acc.x *= inv; acc.y *= inv; acc.z *= inv; acc.w *= inv;
    ((float4*)(g_agg + (size_t)warp * 128))[lane] = acc;
}

// ---------------- GEMM2 (tf32 tensor cores) + fused BN2 stats --------------
// A = [agg2 | bn1relu(x1)]; BN1 applied in the A-loader for the x1 half.
__global__ void __launch_bounds__(256) k_gemm2(const float* __restrict__ b2) {
    __shared__ uint32_t sA[64][36];    // stride 36 -> conflict-free frag loads
    __shared__ uint32_t sB[32][136];   // stride 136 -> conflict-free frag loads
    __shared__ float s_stat[256];      // [0:128) sum, [128:256) sumsq

    int t = threadIdx.x;
    int warp = t >> 5, lane = t & 31;
    int g = lane >> 2, tg = lane & 3;
    int wm = warp & 3, wn = warp >> 2;
    int n0 = blockIdx.x * 64;

    if (t < 256) s_stat[t] = 0.f;

    float c[8][4];
#pragma unroll
    for (int i = 0; i < 8; i++)
#pragma unroll
        for (int j = 0; j < 4; j++) c[i][j] = 0.f;

    for (int kc = 0; kc < 8; kc++) {
        // A tile: 64 nodes x 32 k (agg2 for kc<4; bn1relu(x1) for kc>=4)
        {
            bool isx1 = (kc >= 4);
            const float* base = isx1 ? g_x1 : g_agg;
            int koff = (kc & 3) * 32;
#pragma unroll
            for (int i = 0; i < 2; i++) {
                int idx = t + i * 256;          // 0..511 float4s
                int row = idx >> 3, kq = idx & 7;
                int node = n0 + row;
                float4 v = make_float4(0, 0, 0, 0);
                if (node < NN)
                    v = *(const float4*)(base + (size_t)node * 128 + koff + kq * 4);
                if (isx1) {
                    int cidx = koff + kq * 4;
                    float4 sc = *(const float4*)(g_bns + cidx);
                    float4 sh = *(const float4*)(g_bns + 128 + cidx);
                    v.x = fmaxf(v.x * sc.x + sh.x, 0.f);
                    v.y = fmaxf(v.y * sc.y + sh.y, 0.f);
                    v.z = fmaxf(v.z * sc.z + sh.z, 0.f);
                    v.w = fmaxf(v.w * sc.w + sh.w, 0.f);
                }
                sA[row][kq * 4 + 0] = f2tf(v.x);
                sA[row][kq * 4 + 1] = f2tf(v.y);
                sA[row][kq * 4 + 2] = f2tf(v.z);
                sA[row][kq * 4 + 3] = f2tf(v.w);
            }
        }
        // B tile: 32 k x 128 n, already tf32 in g_Bt
        {
#pragma unroll
            for (int i = 0; i < 4; i++) {
                int idx = t + i * 256;          // 0..1023 uint4s
                int k = idx >> 5, nq = idx & 31;
                uint4 v = *(const uint4*)(g_Bt + (size_t)(kc * 32 + k) * 128 + nq * 4);
                *(uint4*)&sB[k][nq * 4] = v;
            }
        }
        __syncthreads();
#pragma unroll
        for (int ks = 0; ks < 4; ks++) {
            int k0 = ks * 8;
            uint32_t a0 = sA[wm * 16 + g    ][k0 + tg];
            uint32_t a1 = sA[wm * 16 + g + 8][k0 + tg];
            uint32_t a2 = sA[wm * 16 + g    ][k0 + tg + 4];
            uint32_t a3 = sA[wm * 16 + g + 8][k0 + tg + 4];
#pragma unroll
            for (int nt = 0; nt < 8; nt++) {
                uint32_t b0 = sB[k0 + tg    ][wn * 64 + nt * 8 + g];
                uint32_t b1 = sB[k0 + tg + 4][wn * 64 + nt * 8 + g];
                mma_tf32(c[nt], a0, a1, a2, a3, b0, b1);
            }
        }
        __syncthreads();
    }

    // epilogue: add bias, write h2, accumulate BN2 stats in smem
    int r0 = n0 + wm * 16 + g;
    int r1 = r0 + 8;
#pragma unroll
    for (int nt = 0; nt < 8; nt++) {
        int col = wn * 64 + nt * 8 + tg * 2;
        float bv0 = b2[col], bv1 = b2[col + 1];
        float v00 = c[nt][0] + bv0, v01 = c[nt][1] + bv1;   // row r0
        float v10 = c[nt][2] + bv0, v11 = c[nt][3] + bv1;   // row r1
        float s0 = 0.f, s1 = 0.f, q0 = 0.f, q1 = 0.f;
        if (r0 < NN) {
            *(float2*)(g_h2 + (size_t)r0 * 128 + col) = make_float2(v00, v01);
            s0 += v00; q0 += v00 * v00;
            s1 += v01; q1 += v01 * v01;
        }
        if (r1 < NN) {
            *(float2*)(g_h2 + (size_t)r1 * 128 + col) = make_float2(v10, v11);
            s0 += v10; q0 += v10 * v10;
            s1 += v11; q1 += v11 * v11;
        }
        atomicAdd(&s_stat[col], s0);
        atomicAdd(&s_stat[col + 1], s1);
        atomicAdd(&s_stat[128 + col], q0);
        atomicAdd(&s_stat[128 + col + 1], q1);
    }
    __syncthreads();
    atomicAdd(&g_stat[256 + t], s_stat[t]);
}

// --- BN2+relu(h2) + BN1+relu(x1) + residual + pooling (batch sorted) -------
#define POOL_ROWS 128
__global__ void k_pool2(const int* __restrict__ batch) {
    int c = threadIdx.x;            // channel
    int n0 = blockIdx.x * POOL_ROWS;
    float sc1 = g_bns[c],       sh1 = g_bns[128 + c];
    float sc2 = g_bns[256 + c], sh2 = g_bns[384 + c];
    float acc = 0.f;
    int curg = -1, cnt = 0;
    for (int r = 0; r < POOL_ROWS; r++) {
        int n = n0 + r;
        if (n >= NN) break;
        int gg = batch[n];
        if (gg != curg) {
            if (curg >= 0) {
                atomicAdd(&g_pool[curg * 128 + c], acc);
                if (c == 0) atomicAdd(&g_gcnt[curg], cnt);
            }
            curg = gg; acc = 0.f; cnt = 0;
        }
        float h = g_h2[(size_t)n * 128 + c];
        float xv = g_x1[(size_t)n * 128 + c];
        acc += fmaxf(xv * sc1 + sh1, 0.f) + fmaxf(h * sc2 + sh2, 0.f);
        cnt++;
    }
    if (curg >= 0) {
        atomicAdd(&g_pool[curg * 128 + c], acc);
        if (c == 0) atomicAdd(&g_gcnt[curg], cnt);
    }
}

__global__ void k_out(float* __restrict__ out) {
    int g = blockIdx.x, c = threadIdx.x;
    out[g * 128 + c] = g_pool[g * 128 + c] / fmaxf((float)g_gcnt[g], 1.f);
}

// ---------------- launch ----------------
extern "C" void kernel_launch(void* const* d_in, const int* in_sizes, int n_in,
                              void* d_out, int out_size) {
    const float* x     = (const float*)d_in[0];
    const int*   ei    = (const int*)d_in[1];      // [2, NE] int32
    const int*   batch = (const int*)d_in[2];
    const float* W1l   = (const float*)d_in[3];
    const float* b1    = (const float*)d_in[4];
    const float* W1r   = (const float*)d_in[5];
    const float* g1    = (const float*)d_in[6];
    const float* beta1 = (const float*)d_in[7];
    const float* W2l   = (const float*)d_in[8];
    const float* b2    = (const float*)d_in[9];
    const float* W2r   = (const float*)d_in[10];
    const float* g2    = (const float*)d_in[11];
    const float* beta2 = (const float*)d_in[12];
    float* out = (float*)d_out;

    const int* src = ei;
    const int* dst = ei + NE;

    int nScan = (NN + SCAN_T - 1) / SCAN_T;

    k_initw<<<(NN + 255) / 256, 256>>>(W2l, W2r);   // grid covers NN
    k_deg<<<(NE + 255) / 256, 256>>>(dst);
    k_scan1<<<nScan, SCAN_T>>>();
    k_scan2<<<1, 256>>>(nScan);
    k_scan3<<<(NN + 255) / 256, 256>>>();
    k_fill<<<(NE + 255) / 256, 256>>>(src, dst);
    k_agg1<<<(NN + 255) / 256, 256>>>(x);
    k_gemm1<<<(NN + 63) / 64, 128>>>(x, W1l, b1, W1r);
    k_bnprep<<<1, 128>>>(0, g1, beta1);
    k_agg2<<<(NN * 32 + 255) / 256, 256>>>();
    k_gemm2<<<(NN + 63) / 64, 256>>>(b2);
    k_bnprep<<<1, 128>>>(256, g2, beta2);
    k_pool2<<<(NN + POOL_ROWS - 1) / POOL_ROWS, 128>>>(batch);
    k_out<<<128, 128>>>(out);
}